// round 5
// baseline (speedup 1.0000x reference)
#include <cuda_runtime.h>
#include <cuda_bf16.h>
#include <math.h>
#include <stdint.h>

#define T_TOK 4096
#define HID   1024
#define FFN   2816
#define NE    8
#define RMAX  (T_TOK * 2)
#define BM    128
#define BN    64
#define BK    16
#define MT_MAX 80
#define AS    136   // sA[k][m] row stride in floats; 136 mod 32 == 8 -> banks 8k+m conflict-free
#define BS    72    // sB[k][n] row stride; 72 mod 32 == 8

// ---------------- device scratch (allocation-free: __device__ globals) ----------------
__device__ float g_xn[T_TOK * HID];          // normalized activations, fp32
__device__ float g_act[RMAX * FFN];          // SwiGLU activations, fp32 (~92MB)
__device__ int   g_counts[NE];
__device__ int   g_perm[RMAX];               // routed row -> token
__device__ float g_gate[RMAX];               // routed row -> gate prob
__device__ int   g_topi[T_TOK * 2];
__device__ float g_topp[T_TOK * 2];
__device__ int   g_tile_e[MT_MAX];
__device__ int   g_tile_row0[MT_MAX];
__device__ int   g_tile_rows[MT_MAX];
__device__ int   g_nmt;

// ---------------- helpers ----------------
__device__ __forceinline__ unsigned f2tf(float x) {
    unsigned u;
    asm("cvt.rna.tf32.f32 %0, %1;" : "=r"(u) : "f"(x));
    return u;
}

__device__ __forceinline__ void mma_tf32(float c[4], const unsigned a[4], const unsigned b[2]) {
    asm volatile(
        "mma.sync.aligned.m16n8k8.row.col.f32.tf32.tf32.f32 "
        "{%0,%1,%2,%3}, {%4,%5,%6,%7}, {%8,%9}, {%0,%1,%2,%3};"
        : "+f"(c[0]), "+f"(c[1]), "+f"(c[2]), "+f"(c[3])
        : "r"(a[0]), "r"(a[1]), "r"(a[2]), "r"(a[3]), "r"(b[0]), "r"(b[1]));
}

// ---------------- kernel 0: zero output + counts ----------------
__global__ void k_zero(float* __restrict__ out, int n) {
    int gi = blockIdx.x * blockDim.x + threadIdx.x;
    for (int i = gi; i < n; i += gridDim.x * blockDim.x) out[i] = 0.0f;
    if (gi < NE) g_counts[gi] = 0;
}

// ---------------- kernel 1: RMSNorm + router + top2 ----------------
// grid = T_TOK blocks, 128 threads; each thread owns 8 hidden elements
__global__ void k_rms_router(const float* __restrict__ x,
                             const float* __restrict__ lnw,
                             const float* __restrict__ rw) {
    int t = blockIdx.x;
    int tid = threadIdx.x;
    int lane = tid & 31, w = tid >> 5;
    int h0 = tid * 8;

    const float* xr = x + (size_t)t * HID;
    float4 v0 = *(const float4*)(xr + h0);
    float4 v1 = *(const float4*)(xr + h0 + 4);

    float ss = v0.x * v0.x + v0.y * v0.y + v0.z * v0.z + v0.w * v0.w +
               v1.x * v1.x + v1.y * v1.y + v1.z * v1.z + v1.w * v1.w;
#pragma unroll
    for (int o = 16; o; o >>= 1) ss += __shfl_xor_sync(0xffffffffu, ss, o);

    __shared__ float s_red[4];
    __shared__ float s_l[4][8];
    __shared__ float s_rstd;
    if (lane == 0) s_red[w] = ss;
    __syncthreads();
    if (tid == 0) {
        float tot = s_red[0] + s_red[1] + s_red[2] + s_red[3];
        s_rstd = rsqrtf(tot / (float)HID + 1e-5f);
    }
    __syncthreads();
    float rstd = s_rstd;

    float4 wa = *(const float4*)(lnw + h0);
    float4 wb = *(const float4*)(lnw + h0 + 4);
    float xn[8];
    xn[0] = v0.x * rstd * wa.x;  xn[1] = v0.y * rstd * wa.y;
    xn[2] = v0.z * rstd * wa.z;  xn[3] = v0.w * rstd * wa.w;
    xn[4] = v1.x * rstd * wb.x;  xn[5] = v1.y * rstd * wb.y;
    xn[6] = v1.z * rstd * wb.z;  xn[7] = v1.w * rstd * wb.w;

    *(float4*)(g_xn + (size_t)t * HID + h0)     = make_float4(xn[0], xn[1], xn[2], xn[3]);
    *(float4*)(g_xn + (size_t)t * HID + h0 + 4) = make_float4(xn[4], xn[5], xn[6], xn[7]);

    // router logits: each thread accumulates 8 experts over its 8 elements
    float l[8] = {0, 0, 0, 0, 0, 0, 0, 0};
#pragma unroll
    for (int j = 0; j < 8; j++) {
        const float4* rp = (const float4*)(rw + (size_t)(h0 + j) * NE);
        float4 r0 = rp[0], r1 = rp[1];
        float xv = xn[j];
        l[0] += xv * r0.x; l[1] += xv * r0.y; l[2] += xv * r0.z; l[3] += xv * r0.w;
        l[4] += xv * r1.x; l[5] += xv * r1.y; l[6] += xv * r1.z; l[7] += xv * r1.w;
    }
#pragma unroll
    for (int o = 16; o; o >>= 1) {
#pragma unroll
        for (int e = 0; e < 8; e++) l[e] += __shfl_xor_sync(0xffffffffu, l[e], o);
    }
    if (lane == 0) {
#pragma unroll
        for (int e = 0; e < 8; e++) s_l[w][e] = l[e];
    }
    __syncthreads();
    if (tid == 0) {
        float lg[8];
#pragma unroll
        for (int e = 0; e < 8; e++) lg[e] = s_l[0][e] + s_l[1][e] + s_l[2][e] + s_l[3][e];
        float mx = lg[0];
#pragma unroll
        for (int e = 1; e < 8; e++) mx = fmaxf(mx, lg[e]);
        float p[8]; float se = 0.0f;
#pragma unroll
        for (int e = 0; e < 8; e++) { p[e] = expf(lg[e] - mx); se += p[e]; }
        float inv = 1.0f / se;
        int i1 = 0;
#pragma unroll
        for (int e = 1; e < 8; e++) if (p[e] > p[i1]) i1 = e;
        int i2 = -1;
#pragma unroll
        for (int e = 0; e < 8; e++) if (e != i1 && (i2 < 0 || p[e] > p[i2])) i2 = e;
        g_topi[2 * t + 0] = i1; g_topp[2 * t + 0] = p[i1] * inv;
        g_topi[2 * t + 1] = i2; g_topp[2 * t + 1] = p[i2] * inv;
        atomicAdd(&g_counts[i1], 1);
        atomicAdd(&g_counts[i2], 1);
    }
}

// ---------------- kernel 2: offsets + scatter + tile map (single block) ----------------
__global__ void k_route() {
    __shared__ int s_cur[NE];
    int tid = threadIdx.x;
    if (tid == 0) {
        int off = 0, nm = 0;
        for (int e = 0; e < NE; e++) {
            s_cur[e] = off;
            int n = g_counts[e];
            for (int m0 = 0; m0 < n; m0 += BM) {
                g_tile_e[nm] = e;
                g_tile_row0[nm] = off + m0;
                g_tile_rows[nm] = min(BM, n - m0);
                nm++;
            }
            off += n;
        }
        g_nmt = nm;
    }
    __syncthreads();
    for (int t = tid; t < T_TOK; t += blockDim.x) {
        for (int k = 0; k < 2; k++) {
            int e = g_topi[2 * t + k];
            int pos = atomicAdd(&s_cur[e], 1);
            g_perm[pos] = t;
            g_gate[pos] = g_topp[2 * t + k];
        }
    }
}

// ---------------- kernel 3: GEMM1 (X@W1, X@W3) + SiLU*mul ----------------
// grid = (FFN/BN, MT_MAX), 256 threads. Warp tile 32x32 per matrix.
__global__ __launch_bounds__(256, 1) void k_gemm1(const float* __restrict__ w1,
                                                  const float* __restrict__ w3) {
    int mt = blockIdx.y;
    if (mt >= g_nmt) return;
    int e = g_tile_e[mt], row0 = g_tile_row0[mt], rows = g_tile_rows[mt];
    int n0 = blockIdx.x * BN;

    __shared__ __align__(16) unsigned sA[2][BK][AS];
    __shared__ __align__(16) unsigned sB1[2][BK][BS];
    __shared__ __align__(16) unsigned sB3[2][BK][BS];
    __shared__ int s_tok[BM];

    int tid = threadIdx.x;
    if (tid < BM) s_tok[tid] = (tid < rows) ? g_perm[row0 + tid] : -1;
    __syncthreads();

    // loader mapping
    int am = tid >> 1;                 // A row 0..127
    int ak = (tid & 1) * 8;            // A k-offset 0 or 8
    int bk = tid >> 4;                 // B k-row 0..15
    int bc = (tid & 15) * 4;           // B col 0..60 step 4
    int atok = s_tok[am];
    const float* ap = (atok >= 0) ? (g_xn + (size_t)atok * HID + ak) : nullptr;
    const float* w1p = w1 + (size_t)e * HID * FFN + (size_t)bk * FFN + n0 + bc;
    const float* w3p = w3 + (size_t)e * HID * FFN + (size_t)bk * FFN + n0 + bc;

    float4 ra0, ra1, rb1, rb3;
    auto ldg_stage = [&](int s) {
        int kg = s * BK;
        if (ap) {
            ra0 = *(const float4*)(ap + kg);
            ra1 = *(const float4*)(ap + kg + 4);
        } else {
            ra0 = make_float4(0, 0, 0, 0);
            ra1 = make_float4(0, 0, 0, 0);
        }
        rb1 = *(const float4*)(w1p + (size_t)kg * FFN);
        rb3 = *(const float4*)(w3p + (size_t)kg * FFN);
    };
    auto sts_stage = [&](int buf) {
        sA[buf][ak + 0][am] = f2tf(ra0.x);
        sA[buf][ak + 1][am] = f2tf(ra0.y);
        sA[buf][ak + 2][am] = f2tf(ra0.z);
        sA[buf][ak + 3][am] = f2tf(ra0.w);
        sA[buf][ak + 4][am] = f2tf(ra1.x);
        sA[buf][ak + 5][am] = f2tf(ra1.y);
        sA[buf][ak + 6][am] = f2tf(ra1.z);
        sA[buf][ak + 7][am] = f2tf(ra1.w);
        *(uint4*)&sB1[buf][bk][bc] = make_uint4(f2tf(rb1.x), f2tf(rb1.y), f2tf(rb1.z), f2tf(rb1.w));
        *(uint4*)&sB3[buf][bk][bc] = make_uint4(f2tf(rb3.x), f2tf(rb3.y), f2tf(rb3.z), f2tf(rb3.w));
    };

    int lane = tid & 31, wz = tid >> 5;
    int mw = (wz & 3) * 32;   // 4 m-warps cover 128 rows
    int nw = (wz >> 2) * 32;  // 2 n-warps cover 64 cols
    int g = lane >> 2, tg = lane & 3;

    float acc1[2][4][4] = {};
    float acc3[2][4][4] = {};

    ldg_stage(0);
    sts_stage(0);
    __syncthreads();

    const int NS = HID / BK;  // 64
    for (int s = 0; s < NS; s++) {
        int buf = s & 1;
        if (s + 1 < NS) ldg_stage(s + 1);
#pragma unroll
        for (int kk = 0; kk < BK; kk += 8) {
            unsigned a[2][4], b1[4][2], b3[4][2];
#pragma unroll
            for (int i = 0; i < 2; i++) {
                int m = mw + i * 16;
                a[i][0] = sA[buf][kk + tg][m + g];
                a[i][1] = sA[buf][kk + tg][m + g + 8];
                a[i][2] = sA[buf][kk + tg + 4][m + g];
                a[i][3] = sA[buf][kk + tg + 4][m + g + 8];
            }
#pragma unroll
            for (int j = 0; j < 4; j++) {
                int n = nw + j * 8 + g;
                b1[j][0] = sB1[buf][kk + tg][n];
                b1[j][1] = sB1[buf][kk + tg + 4][n];
                b3[j][0] = sB3[buf][kk + tg][n];
                b3[j][1] = sB3[buf][kk + tg + 4][n];
            }
#pragma unroll
            for (int i = 0; i < 2; i++)
#pragma unroll
                for (int j = 0; j < 4; j++) {
                    mma_tf32(acc1[i][j], a[i], b1[j]);
                    mma_tf32(acc3[i][j], a[i], b3[j]);
                }
        }
        if (s + 1 < NS) sts_stage((s + 1) & 1);
        __syncthreads();
    }

    // epilogue: act = silu(h1) * h3
#pragma unroll
    for (int i = 0; i < 2; i++) {
        int rb = mw + i * 16 + g;
#pragma unroll
        for (int j = 0; j < 4; j++) {
            int c = nw + j * 8 + tg * 2;
            if (rb < rows) {
                float h1a = acc1[i][j][0], h1b = acc1[i][j][1];
                float h3a = acc3[i][j][0], h3b = acc3[i][j][1];
                float sa = h1a / (1.0f + __expf(-h1a));
                float sb = h1b / (1.0f + __expf(-h1b));
                *(float2*)(g_act + (size_t)(row0 + rb) * FFN + n0 + c) = make_float2(sa * h3a, sb * h3b);
            }
            int rb2 = rb + 8;
            if (rb2 < rows) {
                float h1a = acc1[i][j][2], h1b = acc1[i][j][3];
                float h3a = acc3[i][j][2], h3b = acc3[i][j][3];
                float sa = h1a / (1.0f + __expf(-h1a));
                float sb = h1b / (1.0f + __expf(-h1b));
                *(float2*)(g_act + (size_t)(row0 + rb2) * FFN + n0 + c) = make_float2(sa * h3a, sb * h3b);
            }
        }
    }
}

// ---------------- kernel 4: GEMM2 (act @ W2), gated scatter-add into out ----------------
// grid = (HID/BN, MT_MAX), 256 threads.
__global__ __launch_bounds__(256, 1) void k_gemm2(const float* __restrict__ w2,
                                                  float* __restrict__ out) {
    int mt = blockIdx.y;
    if (mt >= g_nmt) return;
    int e = g_tile_e[mt], row0 = g_tile_row0[mt], rows = g_tile_rows[mt];
    int n0 = blockIdx.x * BN;

    __shared__ __align__(16) unsigned sA[2][BK][AS];
    __shared__ __align__(16) unsigned sB[2][BK][BS];
    __shared__ int   s_tok[BM];
    __shared__ float s_g[BM];

    int tid = threadIdx.x;
    if (tid < BM) {
        bool v = tid < rows;
        s_tok[tid] = v ? g_perm[row0 + tid] : -1;
        s_g[tid]   = v ? g_gate[row0 + tid] : 0.0f;
    }
    __syncthreads();

    int am = tid >> 1;
    int ak = (tid & 1) * 8;
    int bk = tid >> 4;
    int bc = (tid & 15) * 4;
    bool avalid = am < rows;
    const float* ap = g_act + (size_t)(row0 + am) * FFN + ak;
    const float* bp = w2 + (size_t)e * FFN * HID + (size_t)bk * HID + n0 + bc;

    float4 ra0, ra1, rb;
    auto ldg_stage = [&](int s) {
        int kg = s * BK;
        if (avalid) {
            ra0 = *(const float4*)(ap + kg);
            ra1 = *(const float4*)(ap + kg + 4);
        } else {
            ra0 = make_float4(0, 0, 0, 0);
            ra1 = make_float4(0, 0, 0, 0);
        }
        rb = *(const float4*)(bp + (size_t)kg * HID);
    };
    auto sts_stage = [&](int buf) {
        sA[buf][ak + 0][am] = f2tf(ra0.x);
        sA[buf][ak + 1][am] = f2tf(ra0.y);
        sA[buf][ak + 2][am] = f2tf(ra0.z);
        sA[buf][ak + 3][am] = f2tf(ra0.w);
        sA[buf][ak + 4][am] = f2tf(ra1.x);
        sA[buf][ak + 5][am] = f2tf(ra1.y);
        sA[buf][ak + 6][am] = f2tf(ra1.z);
        sA[buf][ak + 7][am] = f2tf(ra1.w);
        *(uint4*)&sB[buf][bk][bc] = make_uint4(f2tf(rb.x), f2tf(rb.y), f2tf(rb.z), f2tf(rb.w));
    };

    int lane = tid & 31, wz = tid >> 5;
    int mw = (wz & 3) * 32;
    int nw = (wz >> 2) * 32;
    int g = lane >> 2, tg = lane & 3;

    float acc[2][4][4] = {};

    ldg_stage(0);
    sts_stage(0);
    __syncthreads();

    const int NS = FFN / BK;  // 176
    for (int s = 0; s < NS; s++) {
        int buf = s & 1;
        if (s + 1 < NS) ldg_stage(s + 1);
#pragma unroll
        for (int kk = 0; kk < BK; kk += 8) {
            unsigned a[2][4], b[4][2];
#pragma unroll
            for (int i = 0; i < 2; i++) {
                int m = mw + i * 16;
                a[i][0] = sA[buf][kk + tg][m + g];
                a[i][1] = sA[buf][kk + tg][m + g + 8];
                a[i][2] = sA[buf][kk + tg + 4][m + g];
                a[i][3] = sA[buf][kk + tg + 4][m + g + 8];
            }
#pragma unroll
            for (int j = 0; j < 4; j++) {
                int n = nw + j * 8 + g;
                b[j][0] = sB[buf][kk + tg][n];
                b[j][1] = sB[buf][kk + tg + 4][n];
            }
#pragma unroll
            for (int i = 0; i < 2; i++)
#pragma unroll
                for (int j = 0; j < 4; j++) mma_tf32(acc[i][j], a[i], b[j]);
        }
        if (s + 1 < NS) sts_stage((s + 1) & 1);
        __syncthreads();
    }

    // epilogue: out[token] += gate * y  (exactly 2 contributions per element -> deterministic)
#pragma unroll
    for (int i = 0; i < 2; i++) {
        int rb0 = mw + i * 16 + g;
#pragma unroll
        for (int j = 0; j < 4; j++) {
            int c = nw + j * 8 + tg * 2;
            if (rb0 < rows) {
                int tk = s_tok[rb0];
                float gg = s_g[rb0];
                atomicAdd(&out[(size_t)tk * HID + n0 + c], gg * acc[i][j][0]);
                atomicAdd(&out[(size_t)tk * HID + n0 + c + 1], gg * acc[i][j][1]);
            }
            int rb2 = rb0 + 8;
            if (rb2 < rows) {
                int tk = s_tok[rb2];
                float gg = s_g[rb2];
                atomicAdd(&out[(size_t)tk * HID + n0 + c], gg * acc[i][j][2]);
                atomicAdd(&out[(size_t)tk * HID + n0 + c + 1], gg * acc[i][j][3]);
            }
        }
    }
}

// ---------------- launch ----------------
extern "C" void kernel_launch(void* const* d_in, const int* in_sizes, int n_in,
                              void* d_out, int out_size) {
    const float* hs  = (const float*)d_in[0];  // hidden_states [2,2048,1024]
    const float* lnw = (const float*)d_in[1];  // ln_weight [1024]
    const float* rw  = (const float*)d_in[2];  // router_w [1024,8]
    const float* w1  = (const float*)d_in[3];  // [8,1024,2816]
    const float* w3  = (const float*)d_in[4];  // [8,1024,2816]
    const float* w2  = (const float*)d_in[5];  // [8,2816,1024]
    float* out = (float*)d_out;                // [2,2048,1024] fp32

    k_zero<<<2048, 256>>>(out, out_size);
    k_rms_router<<<T_TOK, 128>>>(hs, lnw, rw);
    k_route<<<1, 256>>>();
    dim3 g1(FFN / BN, MT_MAX);
    k_gemm1<<<g1, 256>>>(w1, w3);
    dim3 g2(HID / BN, MT_MAX);
    k_gemm2<<<g2, 256>>>(w2, out);
}